// round 2
// baseline (speedup 1.0000x reference)
#include <cuda_runtime.h>

#define B 2
#define N 2048
#define C 768
#define CG 192          // C/4 float4 groups
#define ROWCHUNKS 32    // K1: 64 rows per chunk
#define JGROUPS 48      // K4: 16 j-rows per group

__device__ float4 g_part[B][ROWCHUNKS][CG];  // partial column sums of X
__device__ float  g_s[B][C];                 // s_b = sum_n X[b,n,:]
__device__ float  g_u[B][C];                 // u_b = Wk s_b
__device__ float4 g_vpart[B][JGROUPS][CG];   // partials of v = Wq^T u
__device__ float  g_v[B][C];                 // v_b

__device__ __forceinline__ float4 f4add(float4 a, float4 b) {
    return make_float4(a.x + b.x, a.y + b.y, a.z + b.z, a.w + b.w);
}
__device__ __forceinline__ float4 f4fma(float4 a, float s, float4 acc) {
    return make_float4(fmaf(a.x, s, acc.x), fmaf(a.y, s, acc.y),
                       fmaf(a.z, s, acc.z), fmaf(a.w, s, acc.w));
}

// K1: partial column sums of X. grid (ROWCHUNKS, B), block 192.
__global__ void k_colsum_part(const float4* __restrict__ X4) {
    int b = blockIdx.y;
    int chunk = blockIdx.x;
    int cg = threadIdx.x;
    const float4* p = X4 + ((size_t)b * N + (size_t)chunk * 64) * CG + cg;
    float4 acc = make_float4(0.f, 0.f, 0.f, 0.f);
#pragma unroll 8
    for (int r = 0; r < 64; ++r)
        acc = f4add(acc, p[(size_t)r * CG]);
    g_part[b][chunk][cg] = acc;
}

// K2: reduce ROWCHUNKS partials -> s. grid (B), block 192.
__global__ void k_colsum_reduce() {
    int b = blockIdx.x;
    int cg = threadIdx.x;
    float4 acc = make_float4(0.f, 0.f, 0.f, 0.f);
#pragma unroll
    for (int k = 0; k < ROWCHUNKS; ++k)
        acc = f4add(acc, g_part[b][k][cg]);
    ((float4*)g_s[b])[cg] = acc;
}

// K3: u = Wk @ s for both batches. One warp per output row j. grid 96, block 256.
__global__ void k_wk_matvec(const float4* __restrict__ W4) {
    int j = blockIdx.x * 8 + (threadIdx.x >> 5);
    int lane = threadIdx.x & 31;
    const float4* row = W4 + (size_t)(C + j) * CG;
    const float4* s0 = (const float4*)g_s[0];
    const float4* s1 = (const float4*)g_s[1];
    float a0 = 0.f, a1 = 0.f;
#pragma unroll
    for (int k = 0; k < 6; ++k) {
        int c4 = lane + k * 32;
        float4 w = row[c4];
        float4 v0 = s0[c4];
        float4 v1 = s1[c4];
        a0 += w.x * v0.x + w.y * v0.y + w.z * v0.z + w.w * v0.w;
        a1 += w.x * v1.x + w.y * v1.y + w.z * v1.z + w.w * v1.w;
    }
#pragma unroll
    for (int o = 16; o > 0; o >>= 1) {
        a0 += __shfl_down_sync(0xFFFFFFFFu, a0, o);
        a1 += __shfl_down_sync(0xFFFFFFFFu, a1, o);
    }
    if (lane == 0) {
        g_u[0][j] = a0;
        g_u[1][j] = a1;
    }
}

// K4: partials of v = Wq^T @ u. grid (JGROUPS), block 192.
// Block jy handles j in [jy*16, jy*16+16) over ALL 768 cols (float4 per thread).
__global__ void k_wqT_part(const float4* __restrict__ W4) {
    __shared__ float u0s[16], u1s[16];
    int jy = blockIdx.x;
    int cg = threadIdx.x;
    int j0 = jy * 16;
    if (threadIdx.x < 16) {
        u0s[threadIdx.x] = g_u[0][j0 + threadIdx.x];
        u1s[threadIdx.x] = g_u[1][j0 + threadIdx.x];
    }
    __syncthreads();
    float4 a0 = make_float4(0.f, 0.f, 0.f, 0.f);
    float4 a1 = make_float4(0.f, 0.f, 0.f, 0.f);
#pragma unroll
    for (int jj = 0; jj < 16; ++jj) {
        float4 w = W4[(size_t)(j0 + jj) * CG + cg];
        a0 = f4fma(w, u0s[jj], a0);
        a1 = f4fma(w, u1s[jj], a1);
    }
    g_vpart[0][jy][cg] = a0;
    g_vpart[1][jy][cg] = a1;
}

// K5: reduce JGROUPS partials -> v. grid (B), block 192.
__global__ void k_v_reduce() {
    int b = blockIdx.x;
    int cg = threadIdx.x;
    float4 acc = make_float4(0.f, 0.f, 0.f, 0.f);
#pragma unroll
    for (int k = 0; k < JGROUPS; ++k)
        acc = f4add(acc, g_vpart[b][k][cg]);
    ((float4*)g_v[b])[cg] = acc;
}

// K6: scores[b,n] = 0.125 * dot(X[b,n,:], v[b,:]).
// grid (256, B), block 256 = 8 warps, 1 row per warp.
__global__ void k_scores(const float4* __restrict__ X4, float* __restrict__ out) {
    __shared__ float4 vs[CG];
    int b = blockIdx.y;
    int rowBase = blockIdx.x * 8;
    if (threadIdx.x < CG)
        vs[threadIdx.x] = ((const float4*)g_v[b])[threadIdx.x];
    __syncthreads();
    int warp = threadIdx.x >> 5;
    int lane = threadIdx.x & 31;
    int n = rowBase + warp;
    const float4* x = X4 + ((size_t)b * N + n) * CG;
    float a = 0.f;
#pragma unroll
    for (int k = 0; k < 6; ++k) {
        int c4 = lane + k * 32;
        float4 xv = x[c4];
        float4 vv = vs[c4];
        a += xv.x * vv.x + xv.y * vv.y + xv.z * vv.z + xv.w * vv.w;
    }
#pragma unroll
    for (int o = 16; o > 0; o >>= 1)
        a += __shfl_down_sync(0xFFFFFFFFu, a, o);
    if (lane == 0)
        out[b * N + n] = 0.125f * a;
}

extern "C" void kernel_launch(void* const* d_in, const int* in_sizes, int n_in,
                              void* d_out, int out_size) {
    const float4* X4 = (const float4*)d_in[0];  // [2, 2048, 768] f32
    const float4* W4 = (const float4*)d_in[1];  // [1536, 768] f32
    float* out = (float*)d_out;                 // [2, 2048] f32
    (void)in_sizes; (void)n_in; (void)out_size;

    k_colsum_part<<<dim3(ROWCHUNKS, B), 192>>>(X4);
    k_colsum_reduce<<<B, 192>>>();
    k_wk_matvec<<<96, 256>>>(W4);
    k_wqT_part<<<JGROUPS, 192>>>(W4);
    k_v_reduce<<<B, 192>>>();
    k_scores<<<dim3(256, B), 256>>>(X4, out);
}

// round 4
// speedup vs baseline: 1.3367x; 1.3367x over previous
#include <cuda_runtime.h>

#define B 2
#define N 2048
#define C 768
#define CG 192           // C/4 float4 groups
#define G 128            // grid size (co-resident, 1 wave)
#define T 256            // block size

__device__ float4 g_part[B][64][CG];    // P1 output: 64 partial colsums per batch
__device__ float  g_s[B][C];            // s_b = sum_n X[b,n,:]
__device__ float  g_u[B][C];            // u_b = Wk s_b
__device__ float4 g_vpart[B][G][CG];    // P4 output: per-CTA partials of v
__device__ float  g_v[B][C];            // v_b = Wq^T u_b
__device__ unsigned g_bar[8];           // monotonic barrier counters (zero-init)

__device__ __forceinline__ float4 f4add(float4 a, float4 b) {
    return make_float4(a.x + b.x, a.y + b.y, a.z + b.z, a.w + b.w);
}
__device__ __forceinline__ float4 f4fma(float4 a, float s, float4 acc) {
    return make_float4(fmaf(a.x, s, acc.x), fmaf(a.y, s, acc.y),
                       fmaf(a.z, s, acc.z), fmaf(a.w, s, acc.w));
}

// Grid-wide barrier. Monotonic counter: each launch adds exactly G arrivals per
// barrier slot, so (old/G+1)*G is the release target — no reset needed across
// graph replays. Every thread fences (release) before the block arrives; the
// waiter fences (acquire) after the spin.
__device__ __forceinline__ void grid_barrier(int i) {
    __threadfence();                    // release: order THIS thread's writes
    __syncthreads();
    if (threadIdx.x == 0) {
        unsigned old = atomicAdd(&g_bar[i], 1u);
        unsigned target = (old / G + 1u) * G;
        volatile unsigned* p = &g_bar[i];
        while (*p < target) __nanosleep(64);
        __threadfence();                // acquire
    }
    __syncthreads();
}

__global__ void __launch_bounds__(T, 1)
fused_att_scores(const float4* __restrict__ X4, const float4* __restrict__ W4,
                 float* __restrict__ out) {
    __shared__ float4 sh[2 * CG];   // reused across phases (6 KB)
    const int ct  = blockIdx.x;
    const int tid = threadIdx.x;

    // ---- P1: partial column sums of X. CTA (b, chunk): 32 rows. ----
    {
        int b = ct & 1, chunk = ct >> 1;              // 64 chunks per batch
        if (tid < CG) {
            const float4* p = X4 + ((size_t)b * N + (size_t)chunk * 32) * CG + tid;
            float4 acc = make_float4(0.f, 0.f, 0.f, 0.f);
#pragma unroll 8
            for (int r = 0; r < 32; ++r)
                acc = f4add(acc, p[(size_t)r * CG]);
            g_part[b][chunk][tid] = acc;
        }
    }
    grid_barrier(0);

    // ---- P2: reduce 64 partials -> s. 8 CTAs: (b, quarter of the 192 cols). ----
    if (ct < 8) {
        int b = ct & 1, qs = ct >> 1;                 // qs in [0,4)
        if (tid < 192) {
            int gi = tid % 48, sl = tid / 48;         // 4 slices of 16 partials
            float4 acc = make_float4(0.f, 0.f, 0.f, 0.f);
#pragma unroll
            for (int k = 0; k < 16; ++k)
                acc = f4add(acc, g_part[b][sl * 16 + k][qs * 48 + gi]);
            sh[tid] = acc;
        }
        __syncthreads();
        if (tid < 48) {
            float4 v = f4add(f4add(sh[tid], sh[tid + 48]),
                             f4add(sh[tid + 96], sh[tid + 144]));
            ((float4*)g_s[b])[qs * 48 + tid] = v;
        }
    }
    grid_barrier(1);

    // ---- P3: u = Wk s (both batches). CTA handles 6 j-rows, 1 warp each. ----
    {
        // stage s for BOTH batches into shared: 384 float4 slots, 256 threads
        for (int i = tid; i < 2 * CG; i += T)
            sh[i] = (i < CG) ? ((const float4*)g_s[0])[i]
                             : ((const float4*)g_s[1])[i - CG];
        __syncthreads();
        int wid = tid >> 5, lane = tid & 31;
        if (wid < 6) {
            int j = ct * 6 + wid;
            const float4* row = W4 + (size_t)(C + j) * CG;   // Wk half
            float a0 = 0.f, a1 = 0.f;
#pragma unroll
            for (int k = 0; k < 6; ++k) {
                int c4 = lane + k * 32;
                float4 w  = row[c4];
                float4 v0 = sh[c4];
                float4 v1 = sh[CG + c4];
                a0 += w.x * v0.x + w.y * v0.y + w.z * v0.z + w.w * v0.w;
                a1 += w.x * v1.x + w.y * v1.y + w.z * v1.z + w.w * v1.w;
            }
#pragma unroll
            for (int o = 16; o > 0; o >>= 1) {
                a0 += __shfl_down_sync(0xFFFFFFFFu, a0, o);
                a1 += __shfl_down_sync(0xFFFFFFFFu, a1, o);
            }
            if (lane == 0) { g_u[0][j] = a0; g_u[1][j] = a1; }
        }
    }
    grid_barrier(2);

    // ---- P4: vpart = Wq^T u partials. CTA handles 6 j-rows over all cols. ----
    {
        int j0 = ct * 6;
        if (tid < CG) {
            float4 a0 = make_float4(0.f, 0.f, 0.f, 0.f);
            float4 a1 = make_float4(0.f, 0.f, 0.f, 0.f);
#pragma unroll
            for (int jj = 0; jj < 6; ++jj) {
                float4 w = W4[(size_t)(j0 + jj) * CG + tid]; // Wq half
                a0 = f4fma(w, g_u[0][j0 + jj], a0);
                a1 = f4fma(w, g_u[1][j0 + jj], a1);
            }
            g_vpart[0][ct][tid] = a0;
            g_vpart[1][ct][tid] = a1;
        }
    }
    grid_barrier(3);

    // ---- P5: reduce G partials -> v. 8 CTAs, 4 slices of 32. ----
    if (ct < 8) {
        int b = ct & 1, qs = ct >> 1;
        if (tid < 192) {
            int gi = tid % 48, sl = tid / 48;
            float4 acc = make_float4(0.f, 0.f, 0.f, 0.f);
#pragma unroll
            for (int k = 0; k < 32; ++k)
                acc = f4add(acc, g_vpart[b][sl * 32 + k][qs * 48 + gi]);
            sh[tid] = acc;
        }
        __syncthreads();
        if (tid < 48) {
            float4 v = f4add(f4add(sh[tid], sh[tid + 48]),
                             f4add(sh[tid + 96], sh[tid + 144]));
            ((float4*)g_v[b])[qs * 48 + tid] = v;
        }
    }
    grid_barrier(4);

    // ---- P6: scores[b,n] = 0.125 * X[b,n,:] . v[b]. CTA: 32 rows. ----
    {
        int b = ct & 1, rowblock = ct >> 1;            // 64 rowblocks of 32 rows
        if (tid < CG) sh[tid] = ((const float4*)g_v[b])[tid];
        __syncthreads();
        int wid = tid >> 5, lane = tid & 31;
        int nbase = rowblock * 32 + wid * 4;
        float a[4];
#pragma unroll
        for (int r = 0; r < 4; ++r) {
            const float4* x = X4 + ((size_t)b * N + (nbase + r)) * CG;
            float acc = 0.f;
#pragma unroll
            for (int k = 0; k < 6; ++k) {
                int c4 = lane + k * 32;
                float4 xv = x[c4];
                float4 vv = sh[c4];
                acc += xv.x * vv.x + xv.y * vv.y + xv.z * vv.z + xv.w * vv.w;
            }
            a[r] = acc;
        }
#pragma unroll
        for (int o = 16; o > 0; o >>= 1) {
#pragma unroll
            for (int r = 0; r < 4; ++r)
                a[r] += __shfl_down_sync(0xFFFFFFFFu, a[r], o);
        }
        if (lane == 0) {
#pragma unroll
            for (int r = 0; r < 4; ++r)
                out[b * N + nbase + r] = 0.125f * a[r];
        }
    }
}

extern "C" void kernel_launch(void* const* d_in, const int* in_sizes, int n_in,
                              void* d_out, int out_size) {
    const float4* X4 = (const float4*)d_in[0];  // [2, 2048, 768] f32
    const float4* W4 = (const float4*)d_in[1];  // [1536, 768] f32
    float* out = (float*)d_out;                 // [2, 2048] f32
    (void)in_sizes; (void)n_in; (void)out_size;

    fused_att_scores<<<G, T>>>(X4, W4, out);
}